// round 1
// baseline (speedup 1.0000x reference)
#include <cuda_runtime.h>

#define NN 200000
#define NE 6400000
#define NG 1024
#define NEMB 1032

// Scratch (device globals; allocation-free per harness rules)
__device__ float4 g_hs[NN * 4];          // per-node scaled features hs = h*dis (16 floats)
__device__ float4 g_t[NN * 4];           // per-node edge accumulators
__device__ float  g_dis[NN];             // deg, then rsqrt(deg+1)
__device__ float4 g_tab[NEMB * 4];       // emb @ W1   [1032,16]
__device__ float4 g_pool[2 * NG * 4];    // pooled sums (r then l)
__device__ float  g_cnt[2 * NG];         // node counts per graph

__device__ __forceinline__ void red_add_v4(float4* addr, float4 v) {
    asm volatile("red.global.add.v4.f32 [%0], {%1,%2,%3,%4};"
                 :: "l"(addr), "f"(v.x), "f"(v.y), "f"(v.z), "f"(v.w)
                 : "memory");
}

// Precompute tab = emb @ W1  (1032 x 16)
__global__ void k_tab(const float* __restrict__ emb, const float* __restrict__ W1) {
    __shared__ float Ws[256];
    if (threadIdx.x < 256) Ws[threadIdx.x] = W1[threadIdx.x];
    __syncthreads();
    int r = blockIdx.x * blockDim.x + threadIdx.x;
    if (r >= NEMB) return;
    const float* x = emb + r * 16;
    float acc[16];
#pragma unroll
    for (int j = 0; j < 16; j++) acc[j] = 0.f;
#pragma unroll
    for (int k = 0; k < 16; k++) {
        float xk = __ldg(x + k);
#pragma unroll
        for (int j = 0; j < 16; j++) acc[j] += xk * Ws[k * 16 + j];
    }
    float4* o = g_tab + r * 4;
#pragma unroll
    for (int c = 0; c < 4; c++)
        o[c] = make_float4(acc[4*c], acc[4*c+1], acc[4*c+2], acc[4*c+3]);
}

// Zero pooling buffers (once per launch)
__global__ void k_zero_pool() {
    int i = blockIdx.x * blockDim.x + threadIdx.x;
    if (i < 2 * NG * 4) g_pool[i] = make_float4(0.f, 0.f, 0.f, 0.f);
    if (i < 2 * NG) g_cnt[i] = 0.f;
}

// Zero per-graph node scratch (t accumulators + deg)
__global__ void k_zero() {
    int i = blockIdx.x * blockDim.x + threadIdx.x;
    if (i < NN * 4) g_t[i] = make_float4(0.f, 0.f, 0.f, 0.f);
    if (i < NN) g_dis[i] = 0.f;
}

// In-degree (over dst)
__global__ void k_deg(const int* __restrict__ dst) {
    int e = blockIdx.x * blockDim.x + threadIdx.x;
    if (e >= NE) return;
    atomicAdd(&g_dis[__ldg(dst + e)], 1.0f);
}

// dis = rsqrt(deg+1); hs1 = tab[ids[i]] * dis; count nodes per graph
__global__ void k_embed(const int* __restrict__ ids, const int* __restrict__ batch, int gsel) {
    int i = blockIdx.x * blockDim.x + threadIdx.x;
    if (i >= NN) return;
    float d = rsqrtf(g_dis[i] + 1.0f);
    g_dis[i] = d;
    int id = __ldg(ids + i);
    const float4* t = g_tab + id * 4;
    float4* o = g_hs + i * 4;
#pragma unroll
    for (int c = 0; c < 4; c++) {
        float4 v = __ldg(t + c);
        o[c] = make_float4(v.x * d, v.y * d, v.z * d, v.w * d);
    }
    atomicAdd(&g_cnt[gsel * NG + __ldg(batch + i)], 1.0f);
}

// Edge aggregation: t[dst] += hs[src]   (the hot kernel)
__global__ void k_edge(const int* __restrict__ ei) {
    int e = blockIdx.x * blockDim.x + threadIdx.x;
    if (e >= NE) return;
    int s = __ldg(ei + e);
    int d = __ldg(ei + NE + e);
    const float4* hp = g_hs + (size_t)s * 4;
    float4 v0 = __ldg(hp + 0);
    float4 v1 = __ldg(hp + 1);
    float4 v2 = __ldg(hp + 2);
    float4 v3 = __ldg(hp + 3);
    float4* tp = g_t + (size_t)d * 4;
    red_add_v4(tp + 0, v0);
    red_add_v4(tp + 1, v1);
    red_add_v4(tp + 2, v2);
    red_add_v4(tp + 3, v3);
}

// Layer-1 epilogue + layer-2 prologue:
// y = relu(dis*(t+hs) + b1);  hs2 = (y @ W2) * dis;  t := 0
__global__ void k_post1(const float* __restrict__ W2, const float* __restrict__ b1) {
    __shared__ float Ws[256];
    __shared__ float bs[16];
    if (threadIdx.x < 256) Ws[threadIdx.x] = W2[threadIdx.x];
    if (threadIdx.x < 16) bs[threadIdx.x] = b1[threadIdx.x];
    __syncthreads();
    int i = blockIdx.x * blockDim.x + threadIdx.x;
    if (i >= NN) return;
    float d = g_dis[i];
    float4* tp = g_t + (size_t)i * 4;
    float4* hp = g_hs + (size_t)i * 4;
    float y[16];
#pragma unroll
    for (int c = 0; c < 4; c++) {
        float4 t = tp[c];
        float4 h = hp[c];
        y[4*c+0] = fmaxf(d * (t.x + h.x) + bs[4*c+0], 0.f);
        y[4*c+1] = fmaxf(d * (t.y + h.y) + bs[4*c+1], 0.f);
        y[4*c+2] = fmaxf(d * (t.z + h.z) + bs[4*c+2], 0.f);
        y[4*c+3] = fmaxf(d * (t.w + h.w) + bs[4*c+3], 0.f);
    }
    float acc[16];
#pragma unroll
    for (int j = 0; j < 16; j++) acc[j] = 0.f;
#pragma unroll
    for (int k = 0; k < 16; k++) {
        float yk = y[k];
#pragma unroll
        for (int j = 0; j < 16; j++) acc[j] += yk * Ws[k * 16 + j];
    }
#pragma unroll
    for (int c = 0; c < 4; c++) {
        hp[c] = make_float4(acc[4*c] * d, acc[4*c+1] * d, acc[4*c+2] * d, acc[4*c+3] * d);
        tp[c] = make_float4(0.f, 0.f, 0.f, 0.f);
    }
}

// Layer-2 epilogue + pooling: out2 = dis*(t+hs2) + b2; pool[graph] += out2
__global__ void k_post2(const float* __restrict__ b2, const int* __restrict__ batch, int gsel) {
    __shared__ float bs[16];
    if (threadIdx.x < 16) bs[threadIdx.x] = b2[threadIdx.x];
    __syncthreads();
    int i = blockIdx.x * blockDim.x + threadIdx.x;
    if (i >= NN) return;
    float d = g_dis[i];
    const float4* tp = g_t + (size_t)i * 4;
    const float4* hp = g_hs + (size_t)i * 4;
    int g = __ldg(batch + i);
    float4* pp = g_pool + ((size_t)(gsel * NG + g)) * 4;
#pragma unroll
    for (int c = 0; c < 4; c++) {
        float4 t = tp[c];
        float4 h = hp[c];
        float4 o;
        o.x = d * (t.x + h.x) + bs[4*c+0];
        o.y = d * (t.y + h.y) + bs[4*c+1];
        o.z = d * (t.z + h.z) + bs[4*c+2];
        o.w = d * (t.w + h.w) + bs[4*c+3];
        red_add_v4(pp + c, o);
    }
}

// Mean pool + concat + FC head; outputs laid out as [1024,3] then [1024,3]
__global__ void k_final(const float* __restrict__ fcW, const float* __restrict__ fcb,
                        float* __restrict__ out) {
    int b = blockIdx.x * blockDim.x + threadIdx.x;
    if (b >= NG) return;
    float inv_r = 1.0f / fmaxf(g_cnt[b], 1.0f);
    float inv_l = 1.0f / fmaxf(g_cnt[NG + b], 1.0f);
    const float4* pr = g_pool + (size_t)b * 4;
    const float4* pl = g_pool + (size_t)(NG + b) * 4;
    float v[32];
#pragma unroll
    for (int c = 0; c < 4; c++) {
        float4 r = pr[c];
        v[4*c+0] = r.x * inv_r; v[4*c+1] = r.y * inv_r;
        v[4*c+2] = r.z * inv_r; v[4*c+3] = r.w * inv_r;
        float4 l = pl[c];
        v[16+4*c+0] = l.x * inv_l; v[16+4*c+1] = l.y * inv_l;
        v[16+4*c+2] = l.z * inv_l; v[16+4*c+3] = l.w * inv_l;
    }
#pragma unroll
    for (int o = 0; o < 6; o++) {
        float s = __ldg(fcb + o);
#pragma unroll
        for (int j = 0; j < 32; j++) s += v[j] * __ldg(fcW + o * 32 + j);
        if (o < 3) out[b * 3 + o] = s;
        else       out[NG * 3 + b * 3 + (o - 3)] = s;
    }
}

extern "C" void kernel_launch(void* const* d_in, const int* in_sizes, int n_in,
                              void* d_out, int out_size) {
    const float* emb = (const float*)d_in[0];
    const float* W1  = (const float*)d_in[1];
    const float* b1  = (const float*)d_in[2];
    const float* W2  = (const float*)d_in[3];
    const float* b2  = (const float*)d_in[4];
    const float* fcW = (const float*)d_in[5];
    const float* fcb = (const float*)d_in[6];
    const int* ids_g[2]   = { (const int*)d_in[7],  (const int*)d_in[10] };
    const int* ei_g[2]    = { (const int*)d_in[8],  (const int*)d_in[11] };
    const int* batch_g[2] = { (const int*)d_in[9],  (const int*)d_in[12] };
    float* out = (float*)d_out;

    const int NB_NODE = (NN + 255) / 256;        // 782
    const int NB_EDGE = (NE + 255) / 256;        // 25000
    const int NB_ZERO = (NN * 4 + 255) / 256;    // 3125

    k_tab<<<(NEMB + 255) / 256, 256>>>(emb, W1);
    k_zero_pool<<<(2 * NG * 4 + 255) / 256, 256>>>();

    for (int g = 0; g < 2; g++) {
        const int* ids   = ids_g[g];
        const int* ei    = ei_g[g];
        const int* batch = batch_g[g];

        k_zero<<<NB_ZERO, 256>>>();
        k_deg<<<NB_EDGE, 256>>>(ei + NE);                 // dst half
        k_embed<<<NB_NODE, 256>>>(ids, batch, g);
        k_edge<<<NB_EDGE, 256>>>(ei);                     // layer 1 aggregate
        k_post1<<<NB_NODE, 256>>>(W2, b1);
        k_edge<<<NB_EDGE, 256>>>(ei);                     // layer 2 aggregate
        k_post2<<<NB_NODE, 256>>>(b2, batch, g);
    }

    k_final<<<(NG + 255) / 256, 256>>>(fcW, fcb, out);
}